// round 1
// baseline (speedup 1.0000x reference)
#include <cuda_runtime.h>
#include <cuda_bf16.h>
#include <math_constants.h>

// Problem constants (shapes fixed by the reference)
#define TT 8        // timesteps (B*T)
#define FIN 64      // in features
#define HC 128      // H*C = 2*64
#define CC 64       // per-head channels
#define NMAX 50016
#define EMAX 460000
#define NEG_SLOPE 0.2f

// ---- scratch (device globals; no cudaMalloc allowed) ----
__device__ int   g_deg[NMAX];
__device__ int   g_off[NMAX + 1];
__device__ int   g_cur[NMAX];
__device__ int   g_csr_src[EMAX];
__device__ float g_xl[(size_t)TT * NMAX * HC];   // ~205 MB
__device__ float g_as[(size_t)TT * NMAX * 2];
__device__ float g_ad[(size_t)TT * NMAX * 2];

// ---------------- CSR build ----------------
__global__ void k_zero_deg(int N) {
    int i = blockIdx.x * blockDim.x + threadIdx.x;
    if (i < N) g_deg[i] = 0;
}

__global__ void k_count(const int* __restrict__ dst, int E) {
    int e = blockIdx.x * blockDim.x + threadIdx.x;
    if (e < E) atomicAdd(&g_deg[dst[e]], 1);
}

// single-block scan: offsets (exclusive in g_cur, inclusive shifted in g_off)
__global__ void k_scan(int N) {
    __shared__ int warp_sums[32];
    __shared__ int s_running;
    int tid = threadIdx.x, lane = tid & 31, wid = tid >> 5;
    if (tid == 0) { s_running = 0; g_off[0] = 0; }
    __syncthreads();
    for (int base = 0; base < N; base += 1024) {
        int i = base + tid;
        int v = (i < N) ? g_deg[i] : 0;
        int x = v;
        #pragma unroll
        for (int o = 1; o < 32; o <<= 1) {
            int y = __shfl_up_sync(0xffffffffu, x, o);
            if (lane >= o) x += y;
        }
        if (lane == 31) warp_sums[wid] = x;
        __syncthreads();
        if (wid == 0) {
            int ws = warp_sums[lane];
            #pragma unroll
            for (int o = 1; o < 32; o <<= 1) {
                int y = __shfl_up_sync(0xffffffffu, ws, o);
                if (lane >= o) ws += y;
            }
            warp_sums[lane] = ws;
        }
        __syncthreads();
        int prefix = s_running + (wid > 0 ? warp_sums[wid - 1] : 0) + x; // inclusive
        if (i < N) {
            g_off[i + 1] = prefix;
            g_cur[i] = prefix - v;  // exclusive (fill cursor)
        }
        __syncthreads();
        if (tid == 0) s_running += warp_sums[31];
        __syncthreads();
    }
}

__global__ void k_fill(const int* __restrict__ src, const int* __restrict__ dst, int E) {
    int e = blockIdx.x * blockDim.x + threadIdx.x;
    if (e < E) {
        int pos = atomicAdd(&g_cur[dst[e]], 1);
        g_csr_src[pos] = src[e];
    }
}

// ---------------- GEMM: xl[t][n][hc] = sum_f h[n][t][f] * W[f][hc] ----------------
// block: 256 threads; tile 64 nodes x 128 cols, K=64 (full)
__global__ __launch_bounds__(256) void k_gemm(const float* __restrict__ h,
                                              const float* __restrict__ W, int N) {
    __shared__ float Xs[64][64];    // 16 KB
    __shared__ float Ws[64][128];   // 32 KB
    int t = blockIdx.y;
    int n0 = blockIdx.x * 64;
    int tid = threadIdx.x;

    // load W (8192 floats = 2048 float4)
    const float4* W4 = (const float4*)W;
    float4* Ws4 = (float4*)&Ws[0][0];
    #pragma unroll
    for (int i = 0; i < 8; i++) Ws4[tid + i * 256] = W4[tid + i * 256];
    // load X tile (4096 floats = 1024 float4)
    #pragma unroll
    for (int i = 0; i < 4; i++) {
        int idx = tid + i * 256;
        int row = idx >> 4;
        int c4 = idx & 15;
        int n = n0 + row;
        float4 v = make_float4(0.f, 0.f, 0.f, 0.f);
        if (n < N) v = *(const float4*)(h + ((size_t)n * TT + t) * FIN + c4 * 4);
        *(float4*)(&Xs[row][c4 * 4]) = v;
    }
    __syncthreads();

    int colg = tid & 31;   // cols colg*4 .. colg*4+3
    int rowg = tid >> 5;   // nodes rowg*8 .. rowg*8+7
    float acc[8][4];
    #pragma unroll
    for (int i = 0; i < 8; i++)
        #pragma unroll
        for (int j = 0; j < 4; j++) acc[i][j] = 0.f;

    #pragma unroll
    for (int k = 0; k < 64; k++) {
        float4 b = *(const float4*)(&Ws[k][colg * 4]);
        #pragma unroll
        for (int i = 0; i < 8; i++) {
            float a = Xs[rowg * 8 + i][k];
            acc[i][0] = fmaf(a, b.x, acc[i][0]);
            acc[i][1] = fmaf(a, b.y, acc[i][1]);
            acc[i][2] = fmaf(a, b.z, acc[i][2]);
            acc[i][3] = fmaf(a, b.w, acc[i][3]);
        }
    }

    float* xl = g_xl + (size_t)t * N * HC;
    #pragma unroll
    for (int i = 0; i < 8; i++) {
        int n = n0 + rowg * 8 + i;
        if (n < N)
            *(float4*)(xl + (size_t)n * HC + colg * 4) =
                make_float4(acc[i][0], acc[i][1], acc[i][2], acc[i][3]);
    }
}

// ---------------- per-node attention scores ----------------
// one warp per (t,n): a_s[n][h] = sum_c xl[n][h*64+c]*att_src[h*64+c]
__global__ __launch_bounds__(256) void k_scores(const float* __restrict__ att_src,
                                                const float* __restrict__ att_dst, int N) {
    int gw = (blockIdx.x * blockDim.x + threadIdx.x) >> 5;
    int lane = threadIdx.x & 31;
    if (gw >= TT * N) return;
    int t = gw / N, n = gw - t * N;
    const float* xl = g_xl + ((size_t)t * N + n) * HC;
    float4 v = *(const float4*)(xl + lane * 4);
    float4 as4 = *(const float4*)(att_src + lane * 4);
    float4 ad4 = *(const float4*)(att_dst + lane * 4);
    float ps = v.x * as4.x + v.y * as4.y + v.z * as4.z + v.w * as4.w;
    float pd = v.x * ad4.x + v.y * ad4.y + v.z * ad4.z + v.w * ad4.w;
    #pragma unroll
    for (int o = 8; o; o >>= 1) {
        ps += __shfl_xor_sync(0xffffffffu, ps, o);
        pd += __shfl_xor_sync(0xffffffffu, pd, o);
    }
    if ((lane & 15) == 0) {
        int hh = lane >> 4;
        size_t idx = ((size_t)t * N + n) * 2 + hh;
        g_as[idx] = ps;
        g_ad[idx] = pd;
    }
}

// ---------------- aggregation: softmax-weighted sum over incoming edges ----------------
// one warp per (t, dst-node). 32 lanes cover 128 channels (4 each; lanes 0-15 head0).
__global__ __launch_bounds__(256) void k_agg(const float* __restrict__ bias,
                                             float* __restrict__ out, int N) {
    int gw = (blockIdx.x * blockDim.x + threadIdx.x) >> 5;
    int lane = threadIdx.x & 31;
    if (gw >= TT * N) return;
    int t = gw / N, n = gw - t * N;

    const float* asb = g_as + (size_t)t * N * 2;
    const float* xl = g_xl + (size_t)t * N * HC;
    float2 adv = *(const float2*)(g_ad + ((size_t)t * N + n) * 2);
    float ad0 = adv.x, ad1 = adv.y;

    int s0 = g_off[n], s1 = g_off[n + 1];

    // pass 1: segment max (lanes over edges)
    float m0 = -CUDART_INF_F, m1 = -CUDART_INF_F;
    for (int e = s0 + lane; e < s1; e += 32) {
        int src = g_csr_src[e];
        float2 sv = *(const float2*)(asb + (size_t)src * 2);
        float x0 = sv.x + ad0, x1 = sv.y + ad1;
        x0 = x0 > 0.f ? x0 : NEG_SLOPE * x0;
        x1 = x1 > 0.f ? x1 : NEG_SLOPE * x1;
        m0 = fmaxf(m0, x0);
        m1 = fmaxf(m1, x1);
    }
    #pragma unroll
    for (int o = 16; o; o >>= 1) {
        m0 = fmaxf(m0, __shfl_xor_sync(0xffffffffu, m0, o));
        m1 = fmaxf(m1, __shfl_xor_sync(0xffffffffu, m1, o));
    }

    // pass 2: accumulate sum(ex) and sum(ex * xl[src]) together
    float4 acc = make_float4(0.f, 0.f, 0.f, 0.f);
    float den0 = 0.f, den1 = 0.f;
    for (int e = s0; e < s1; e++) {
        int src = g_csr_src[e];                 // uniform across warp
        float2 sv = *(const float2*)(asb + (size_t)src * 2);
        float x0 = sv.x + ad0, x1 = sv.y + ad1;
        x0 = x0 > 0.f ? x0 : NEG_SLOPE * x0;
        x1 = x1 > 0.f ? x1 : NEG_SLOPE * x1;
        float ex0 = __expf(x0 - m0);
        float ex1 = __expf(x1 - m1);
        den0 += ex0;
        den1 += ex1;
        float4 v = *(const float4*)(xl + (size_t)src * HC + lane * 4);
        float ex = (lane < 16) ? ex0 : ex1;
        acc.x = fmaf(ex, v.x, acc.x);
        acc.y = fmaf(ex, v.y, acc.y);
        acc.z = fmaf(ex, v.z, acc.z);
        acc.w = fmaf(ex, v.w, acc.w);
    }
    float inv_den = 1.f / ((lane < 16) ? den0 : den1);
    acc.x *= inv_den; acc.y *= inv_den; acc.z *= inv_den; acc.w *= inv_den;

    // combine heads: lane l (<16) holds head0 channels c=l*4..l*4+3; lane l+16 head1 same c
    float px = __shfl_down_sync(0xffffffffu, acc.x, 16);
    float py = __shfl_down_sync(0xffffffffu, acc.y, 16);
    float pz = __shfl_down_sync(0xffffffffu, acc.z, 16);
    float pw = __shfl_down_sync(0xffffffffu, acc.w, 16);
    if (lane < 16) {
        float4 b4 = *(const float4*)(bias + lane * 4);
        float4 o4;
        o4.x = 0.5f * (acc.x + px) + b4.x;
        o4.y = 0.5f * (acc.y + py) + b4.y;
        o4.z = 0.5f * (acc.z + pz) + b4.z;
        o4.w = 0.5f * (acc.w + pw) + b4.w;
        o4.x = o4.x > 0.f ? o4.x : (__expf(o4.x) - 1.f);
        o4.y = o4.y > 0.f ? o4.y : (__expf(o4.y) - 1.f);
        o4.z = o4.z > 0.f ? o4.z : (__expf(o4.z) - 1.f);
        o4.w = o4.w > 0.f ? o4.w : (__expf(o4.w) - 1.f);
        // out[b=0][n][t][c], C=64
        *(float4*)(out + ((size_t)n * TT + t) * CC + lane * 4) = o4;
    }
}

extern "C" void kernel_launch(void* const* d_in, const int* in_sizes, int n_in,
                              void* d_out, int out_size) {
    const float* h       = (const float*)d_in[0];
    const int*   src     = (const int*)d_in[1];
    const int*   dst     = (const int*)d_in[2];
    const float* W       = (const float*)d_in[3];
    const float* att_src = (const float*)d_in[4];
    const float* att_dst = (const float*)d_in[5];
    const float* bias    = (const float*)d_in[6];
    float* out = (float*)d_out;

    int E = in_sizes[1];
    int N = in_sizes[0] / (TT * FIN);
    if (N > NMAX) N = NMAX;
    if (E > EMAX) E = EMAX;

    // CSR build (timestep-invariant)
    k_zero_deg<<<(N + 255) / 256, 256>>>(N);
    k_count<<<(E + 255) / 256, 256>>>(dst, E);
    k_scan<<<1, 1024>>>(N);
    k_fill<<<(E + 255) / 256, 256>>>(src, dst, E);

    // GEMM for all timesteps
    dim3 ggrid((N + 63) / 64, TT);
    k_gemm<<<ggrid, 256>>>(h, W, N);

    // per-node attention scores
    int total_warps = TT * N;
    int sblocks = (total_warps * 32 + 255) / 256;
    k_scores<<<sblocks, 256>>>(att_src, att_dst, N);

    // aggregation (softmax + message passing + head mean + bias + elu)
    k_agg<<<sblocks, 256>>>(bias, out, N);
}

// round 2
// speedup vs baseline: 1.0925x; 1.0925x over previous
#include <cuda_runtime.h>
#include <cuda_bf16.h>
#include <math_constants.h>

#define TT 8        // timesteps (B*T)
#define FIN 64      // in features
#define HC 128      // H*C
#define CC 64       // per-head channels
#define NMAX 50016
#define EMAX 460000
#define NEG_SLOPE 0.2f

// ---- scratch (device globals; no cudaMalloc allowed) ----
__device__ int    g_deg[NMAX];
__device__ int    g_off[NMAX + 1];
__device__ int    g_cur[NMAX];
__device__ int    g_csr_src[EMAX];
__device__ int    g_csr_eid[EMAX];
__device__ float  g_xl[(size_t)TT * NMAX * HC];   // ~205 MB
__device__ float  g_as[(size_t)TT * NMAX * 2];
__device__ float  g_ad[(size_t)TT * NMAX * 2];
__device__ float2 g_ex[(size_t)TT * EMAX];        // ~29 MB

// ---------------- CSR build ----------------
__global__ void k_zero_deg(int N) {
    int i = blockIdx.x * blockDim.x + threadIdx.x;
    if (i < N) g_deg[i] = 0;
}

__global__ void k_count(const int* __restrict__ dst, int E) {
    int e = blockIdx.x * blockDim.x + threadIdx.x;
    if (e < E) atomicAdd(&g_deg[dst[e]], 1);
}

__global__ void k_scan(int N) {
    __shared__ int warp_sums[32];
    __shared__ int s_running;
    int tid = threadIdx.x, lane = tid & 31, wid = tid >> 5;
    if (tid == 0) { s_running = 0; g_off[0] = 0; }
    __syncthreads();
    for (int base = 0; base < N; base += 1024) {
        int i = base + tid;
        int v = (i < N) ? g_deg[i] : 0;
        int x = v;
        #pragma unroll
        for (int o = 1; o < 32; o <<= 1) {
            int y = __shfl_up_sync(0xffffffffu, x, o);
            if (lane >= o) x += y;
        }
        if (lane == 31) warp_sums[wid] = x;
        __syncthreads();
        if (wid == 0) {
            int ws = warp_sums[lane];
            #pragma unroll
            for (int o = 1; o < 32; o <<= 1) {
                int y = __shfl_up_sync(0xffffffffu, ws, o);
                if (lane >= o) ws += y;
            }
            warp_sums[lane] = ws;
        }
        __syncthreads();
        int prefix = s_running + (wid > 0 ? warp_sums[wid - 1] : 0) + x; // inclusive
        if (i < N) {
            g_off[i + 1] = prefix;
            g_cur[i] = prefix - v;
        }
        __syncthreads();
        if (tid == 0) s_running += warp_sums[31];
        __syncthreads();
    }
}

__global__ void k_fill(const int* __restrict__ src, const int* __restrict__ dst, int E) {
    int e = blockIdx.x * blockDim.x + threadIdx.x;
    if (e < E) {
        int pos = atomicAdd(&g_cur[dst[e]], 1);
        g_csr_src[pos] = src[e];
        g_csr_eid[pos] = e;
    }
}

// ---------------- GEMM + fused attention scores ----------------
// xl[t][n][hc] = sum_f h[n][t][f] * W[f][hc]; a_s/a_d = dot(xl, att) per head.
// block: 128 threads; tile 64 nodes x 128 cols; 8x8 register tile, k-step 4.
__global__ __launch_bounds__(128) void k_gemm(const float* __restrict__ h,
                                              const float* __restrict__ W,
                                              const float* __restrict__ att_src,
                                              const float* __restrict__ att_dst,
                                              int N) {
    __shared__ float Xs[64][64];    // 16 KB
    __shared__ float Ws[64][128];   // 32 KB
    int t = blockIdx.y;
    int n0 = blockIdx.x * 64;
    int tid = threadIdx.x;

    // load W (2048 float4)
    const float4* W4 = (const float4*)W;
    float4* Ws4 = (float4*)&Ws[0][0];
    #pragma unroll
    for (int i = 0; i < 16; i++) Ws4[tid + i * 128] = W4[tid + i * 128];
    // load X tile (1024 float4)
    #pragma unroll
    for (int i = 0; i < 8; i++) {
        int idx = tid + i * 128;
        int row = idx >> 4;
        int c4 = idx & 15;
        int n = n0 + row;
        float4 v = make_float4(0.f, 0.f, 0.f, 0.f);
        if (n < N) v = *(const float4*)(h + ((size_t)n * TT + t) * FIN + c4 * 4);
        *(float4*)(&Xs[row][c4 * 4]) = v;
    }
    __syncthreads();

    int rowg = tid >> 4;   // 0..7 -> rows rowg*8..+7
    int colg = tid & 15;   // 0..15 -> cols colg*8..+7 (colg<8 => head0)
    float acc[8][8];
    #pragma unroll
    for (int i = 0; i < 8; i++)
        #pragma unroll
        for (int j = 0; j < 8; j++) acc[i][j] = 0.f;

    #pragma unroll
    for (int k4 = 0; k4 < 16; k4++) {
        float4 b0[4], b1[4];
        #pragma unroll
        for (int j = 0; j < 4; j++) {
            b0[j] = *(const float4*)(&Ws[k4 * 4 + j][colg * 8]);
            b1[j] = *(const float4*)(&Ws[k4 * 4 + j][colg * 8 + 4]);
        }
        #pragma unroll
        for (int i = 0; i < 8; i++) {
            float4 av = *(const float4*)(&Xs[rowg * 8 + i][k4 * 4]);
            float aa[4] = {av.x, av.y, av.z, av.w};
            #pragma unroll
            for (int j = 0; j < 4; j++) {
                acc[i][0] = fmaf(aa[j], b0[j].x, acc[i][0]);
                acc[i][1] = fmaf(aa[j], b0[j].y, acc[i][1]);
                acc[i][2] = fmaf(aa[j], b0[j].z, acc[i][2]);
                acc[i][3] = fmaf(aa[j], b0[j].w, acc[i][3]);
                acc[i][4] = fmaf(aa[j], b1[j].x, acc[i][4]);
                acc[i][5] = fmaf(aa[j], b1[j].y, acc[i][5]);
                acc[i][6] = fmaf(aa[j], b1[j].z, acc[i][6]);
                acc[i][7] = fmaf(aa[j], b1[j].w, acc[i][7]);
            }
        }
    }

    // epilogue: store xl + fused attention-score partial dots
    float sa[8], da[8];
    #pragma unroll
    for (int j = 0; j < 8; j++) {
        sa[j] = __ldg(att_src + colg * 8 + j);
        da[j] = __ldg(att_dst + colg * 8 + j);
    }
    float* xl = g_xl + (size_t)t * N * HC;
    int lane = tid & 31;
    #pragma unroll
    for (int i = 0; i < 8; i++) {
        int n = n0 + rowg * 8 + i;
        float ps = 0.f, pd = 0.f;
        #pragma unroll
        for (int j = 0; j < 8; j++) {
            ps = fmaf(acc[i][j], sa[j], ps);
            pd = fmaf(acc[i][j], da[j], pd);
        }
        #pragma unroll
        for (int o = 1; o < 8; o <<= 1) {
            ps += __shfl_xor_sync(0xffffffffu, ps, o);
            pd += __shfl_xor_sync(0xffffffffu, pd, o);
        }
        if (n < N) {
            *(float4*)(xl + (size_t)n * HC + colg * 8) =
                make_float4(acc[i][0], acc[i][1], acc[i][2], acc[i][3]);
            *(float4*)(xl + (size_t)n * HC + colg * 8 + 4) =
                make_float4(acc[i][4], acc[i][5], acc[i][6], acc[i][7]);
            if ((lane & 7) == 0) {
                int head = (lane >> 3) & 1;
                g_as[((size_t)t * N + n) * 2 + head] = ps;
                g_ad[((size_t)t * N + n) * 2 + head] = pd;
            }
        }
    }
}

// ---------------- per-edge exp(leaky(a_s[src]+a_d[dst])), all timesteps ----------------
__global__ __launch_bounds__(256) void k_edge(const int* __restrict__ src,
                                              const int* __restrict__ dst,
                                              int E, int N) {
    int e = blockIdx.x * blockDim.x + threadIdx.x;
    if (e >= E) return;
    int s = src[e], d = dst[e];
    #pragma unroll
    for (int t = 0; t < TT; t++) {
        float2 a = *(const float2*)(g_as + ((size_t)t * N + s) * 2);
        float2 b = *(const float2*)(g_ad + ((size_t)t * N + d) * 2);
        float x0 = a.x + b.x, x1 = a.y + b.y;
        x0 = x0 > 0.f ? x0 : NEG_SLOPE * x0;
        x1 = x1 > 0.f ? x1 : NEG_SLOPE * x1;
        // scores bounded (|x| << 80): exp without max-subtraction is exact-safe
        g_ex[(size_t)t * E + e] = make_float2(__expf(x0), __expf(x1));
    }
}

// ---------------- aggregation: single pass, softmax-normalized weighted sum ----------------
// one warp per (t, dst-node). 32 lanes cover 128 channels; lanes 0-15 head0.
__global__ __launch_bounds__(256) void k_agg(const float* __restrict__ bias,
                                             float* __restrict__ out, int N, int E) {
    int gw = (blockIdx.x * blockDim.x + threadIdx.x) >> 5;
    int lane = threadIdx.x & 31;
    if (gw >= TT * N) return;
    int t = gw / N, n = gw - t * N;

    const float* xl = g_xl + (size_t)t * N * HC;
    const float2* exb = g_ex + (size_t)t * E;
    int s0 = g_off[n], s1 = g_off[n + 1];
    bool h0 = lane < 16;

    float4 acc = make_float4(0.f, 0.f, 0.f, 0.f);
    float den = 0.f;
    #pragma unroll 2
    for (int e = s0; e < s1; e++) {
        int srcn = __ldg(&g_csr_src[e]);   // uniform across warp
        int eid = __ldg(&g_csr_eid[e]);
        float2 exv = __ldg(&exb[eid]);
        float ex = h0 ? exv.x : exv.y;
        den += ex;
        float4 v = *(const float4*)(xl + (size_t)srcn * HC + lane * 4);
        acc.x = fmaf(ex, v.x, acc.x);
        acc.y = fmaf(ex, v.y, acc.y);
        acc.z = fmaf(ex, v.z, acc.z);
        acc.w = fmaf(ex, v.w, acc.w);
    }
    float inv = 1.f / den;
    acc.x *= inv; acc.y *= inv; acc.z *= inv; acc.w *= inv;

    // head mean: lane l (<16) head0 channels c=l*4..+3; lane l+16 head1 same c
    float px = __shfl_down_sync(0xffffffffu, acc.x, 16);
    float py = __shfl_down_sync(0xffffffffu, acc.y, 16);
    float pz = __shfl_down_sync(0xffffffffu, acc.z, 16);
    float pw = __shfl_down_sync(0xffffffffu, acc.w, 16);
    if (h0) {
        float4 b4 = *(const float4*)(bias + lane * 4);
        float4 o4;
        o4.x = 0.5f * (acc.x + px) + b4.x;
        o4.y = 0.5f * (acc.y + py) + b4.y;
        o4.z = 0.5f * (acc.z + pz) + b4.z;
        o4.w = 0.5f * (acc.w + pw) + b4.w;
        o4.x = o4.x > 0.f ? o4.x : (__expf(o4.x) - 1.f);
        o4.y = o4.y > 0.f ? o4.y : (__expf(o4.y) - 1.f);
        o4.z = o4.z > 0.f ? o4.z : (__expf(o4.z) - 1.f);
        o4.w = o4.w > 0.f ? o4.w : (__expf(o4.w) - 1.f);
        *(float4*)(out + ((size_t)n * TT + t) * CC + lane * 4) = o4;
    }
}

extern "C" void kernel_launch(void* const* d_in, const int* in_sizes, int n_in,
                              void* d_out, int out_size) {
    const float* h       = (const float*)d_in[0];
    const int*   src     = (const int*)d_in[1];
    const int*   dst     = (const int*)d_in[2];
    const float* W       = (const float*)d_in[3];
    const float* att_src = (const float*)d_in[4];
    const float* att_dst = (const float*)d_in[5];
    const float* bias    = (const float*)d_in[6];
    float* out = (float*)d_out;

    int E = in_sizes[1];
    int N = in_sizes[0] / (TT * FIN);
    if (N > NMAX) N = NMAX;
    if (E > EMAX) E = EMAX;

    // CSR build (timestep-invariant)
    k_zero_deg<<<(N + 255) / 256, 256>>>(N);
    k_count<<<(E + 255) / 256, 256>>>(dst, E);
    k_scan<<<1, 1024>>>(N);
    k_fill<<<(E + 255) / 256, 256>>>(src, dst, E);

    // GEMM + fused scores for all timesteps
    dim3 ggrid((N + 63) / 64, TT);
    k_gemm<<<ggrid, 128>>>(h, W, att_src, att_dst, N);

    // per-edge exp weights (all timesteps)
    k_edge<<<(E + 255) / 256, 256>>>(src, dst, E, N);

    // aggregation (softmax + message passing + head mean + bias + elu)
    int total_warps = TT * N;
    int ablocks = (total_warps * 32 + 255) / 256;
    k_agg<<<ablocks, 256>>>(bias, out, N, E);
}

// round 4
// speedup vs baseline: 1.1921x; 1.0912x over previous
#include <cuda_runtime.h>
#include <cuda_fp16.h>
#include <cstdint>

#define TT 8        // timesteps (B*T)
#define FIN 64      // in features
#define HC 128      // H*C
#define NMAX 50016
#define EMAX 460000
#define NEG_SLOPE 0.2f

#define XP 68       // Xs row pad (floats) -> conflict-free A-frag LDS
#define WP 136      // Ws row pad (floats) -> conflict-free B-frag LDS
#define GEMM_SMEM (64 * XP * 4 + 64 * WP * 4)   // 52224 B (dynamic)

// ---- scratch (device globals; no cudaMalloc allowed) ----
__device__ int    g_deg[NMAX];
__device__ int    g_off[NMAX + 1];
__device__ int    g_cur[NMAX];
__device__ int    g_csr_src[EMAX];
__device__ int    g_csr_dst[EMAX];
__device__ __half g_xl[(size_t)TT * NMAX * HC];   // fp16, ~102 MB
__device__ float  g_as[(size_t)NMAX * TT * 2];    // [n][t][h]
__device__ float  g_ad[(size_t)NMAX * TT * 2];
__device__ float2 g_ex[(size_t)TT * EMAX];        // [t][csr_pos], ~29 MB

// ---------------- CSR build ----------------
__global__ void k_zero_deg(int N) {
    int i = blockIdx.x * blockDim.x + threadIdx.x;
    if (i < N) g_deg[i] = 0;
}

__global__ void k_count(const int* __restrict__ dst, int E) {
    int e = blockIdx.x * blockDim.x + threadIdx.x;
    if (e < E) atomicAdd(&g_deg[dst[e]], 1);
}

__global__ void k_scan(int N) {
    __shared__ int warp_sums[32];
    __shared__ int s_running;
    int tid = threadIdx.x, lane = tid & 31, wid = tid >> 5;
    if (tid == 0) { s_running = 0; g_off[0] = 0; }
    __syncthreads();
    for (int base = 0; base < N; base += 1024) {
        int i = base + tid;
        int v = (i < N) ? g_deg[i] : 0;
        int x = v;
        #pragma unroll
        for (int o = 1; o < 32; o <<= 1) {
            int y = __shfl_up_sync(0xffffffffu, x, o);
            if (lane >= o) x += y;
        }
        if (lane == 31) warp_sums[wid] = x;
        __syncthreads();
        if (wid == 0) {
            int ws = warp_sums[lane];
            #pragma unroll
            for (int o = 1; o < 32; o <<= 1) {
                int y = __shfl_up_sync(0xffffffffu, ws, o);
                if (lane >= o) ws += y;
            }
            warp_sums[lane] = ws;
        }
        __syncthreads();
        int prefix = s_running + (wid > 0 ? warp_sums[wid - 1] : 0) + x;
        if (i < N) {
            g_off[i + 1] = prefix;
            g_cur[i] = prefix - v;
        }
        __syncthreads();
        if (tid == 0) s_running += warp_sums[31];
        __syncthreads();
    }
}

__global__ void k_fill(const int* __restrict__ src, const int* __restrict__ dst, int E) {
    int e = blockIdx.x * blockDim.x + threadIdx.x;
    if (e < E) {
        int d = dst[e];
        int pos = atomicAdd(&g_cur[d], 1);
        g_csr_src[pos] = src[e];
        g_csr_dst[pos] = d;
    }
}

// ---------------- 3xTF32 tensor-core GEMM + fused scores + fp16 xl ----------------
__device__ __forceinline__ unsigned int f2tf(float x) {
    unsigned int r;
    asm("cvt.rna.tf32.f32 %0, %1;" : "=r"(r) : "f"(x));
    return r;
}

__device__ __forceinline__ void mma8(float* d, unsigned int a0, unsigned int a1,
                                     unsigned int a2, unsigned int a3,
                                     unsigned int b0, unsigned int b1) {
    asm volatile(
        "mma.sync.aligned.m16n8k8.row.col.f32.tf32.tf32.f32 "
        "{%0,%1,%2,%3},{%4,%5,%6,%7},{%8,%9},{%0,%1,%2,%3};"
        : "+f"(d[0]), "+f"(d[1]), "+f"(d[2]), "+f"(d[3])
        : "r"(a0), "r"(a1), "r"(a2), "r"(a3), "r"(b0), "r"(b1));
}

// block 128 thr (4 warps); tile: 64 nodes x 128 cols, K=64.
// warp (wid): rows (wid&1)*32..+31, cols (wid>>1)*64..+63 (one head).
__global__ __launch_bounds__(128, 4) void k_gemm(const float* __restrict__ h,
                                                 const float* __restrict__ W,
                                                 const float* __restrict__ att_src,
                                                 const float* __restrict__ att_dst,
                                                 int N) {
    extern __shared__ float smem[];
    float* Xs = smem;             // [64][XP]
    float* Ws = smem + 64 * XP;   // [64][WP]
    int t = blockIdx.y;
    int n0 = blockIdx.x * 64;
    int tid = threadIdx.x;

    // load W (64x128) into padded smem
    #pragma unroll
    for (int i = 0; i < 16; i++) {
        int idx = tid + i * 128;            // 0..2047 float4s
        int row = idx >> 5, c4 = idx & 31;
        *(float4*)(Ws + row * WP + c4 * 4) = ((const float4*)W)[idx];
    }
    // load X tile (64x64)
    #pragma unroll
    for (int i = 0; i < 8; i++) {
        int idx = tid + i * 128;            // 0..1023 float4s
        int row = idx >> 4, c4 = idx & 15;
        int n = n0 + row;
        float4 v = make_float4(0.f, 0.f, 0.f, 0.f);
        if (n < N) v = *(const float4*)(h + ((size_t)n * TT + t) * FIN + c4 * 4);
        *(float4*)(Xs + row * XP + c4 * 4) = v;
    }
    __syncthreads();

    int wid = tid >> 5, lane = tid & 31;
    int R = (wid & 1) * 32;
    int CB = (wid >> 1) * 64;
    int p = lane >> 2, q = lane & 3;

    float acc[2][8][4];
    #pragma unroll
    for (int rt = 0; rt < 2; rt++)
        #pragma unroll
        for (int nt = 0; nt < 8; nt++)
            #pragma unroll
            for (int c = 0; c < 4; c++) acc[rt][nt][c] = 0.f;

    #pragma unroll
    for (int kt = 0; kt < 8; kt++) {
        unsigned int ah[2][4], al[2][4];
        #pragma unroll
        for (int rt = 0; rt < 2; rt++) {
            int r0 = R + rt * 16 + p;
            int k0 = kt * 8 + q;
            float x0 = Xs[r0 * XP + k0];
            float x1 = Xs[(r0 + 8) * XP + k0];
            float x2 = Xs[r0 * XP + k0 + 4];
            float x3 = Xs[(r0 + 8) * XP + k0 + 4];
            ah[rt][0] = f2tf(x0); al[rt][0] = f2tf(x0 - __uint_as_float(ah[rt][0]));
            ah[rt][1] = f2tf(x1); al[rt][1] = f2tf(x1 - __uint_as_float(ah[rt][1]));
            ah[rt][2] = f2tf(x2); al[rt][2] = f2tf(x2 - __uint_as_float(ah[rt][2]));
            ah[rt][3] = f2tf(x3); al[rt][3] = f2tf(x3 - __uint_as_float(ah[rt][3]));
        }
        #pragma unroll
        for (int nt = 0; nt < 8; nt++) {
            int col = CB + nt * 8 + p;
            float w0 = Ws[(kt * 8 + q) * WP + col];
            float w1 = Ws[(kt * 8 + q + 4) * WP + col];
            unsigned int bh0 = f2tf(w0), bl0 = f2tf(w0 - __uint_as_float(bh0));
            unsigned int bh1 = f2tf(w1), bl1 = f2tf(w1 - __uint_as_float(bh1));
            #pragma unroll
            for (int rt = 0; rt < 2; rt++) {
                mma8(acc[rt][nt], ah[rt][0], ah[rt][1], ah[rt][2], ah[rt][3], bh0, bh1);
                mma8(acc[rt][nt], ah[rt][0], ah[rt][1], ah[rt][2], ah[rt][3], bl0, bl1);
                mma8(acc[rt][nt], al[rt][0], al[rt][1], al[rt][2], al[rt][3], bh0, bh1);
            }
        }
    }

    // ---- fused attention scores (exact fp32 accumulators) ----
    int head = wid >> 1;
    float sa[16], da[16];
    #pragma unroll
    for (int nt = 0; nt < 8; nt++)
        #pragma unroll
        for (int j = 0; j < 2; j++) {
            int col = CB + nt * 8 + q * 2 + j;
            sa[nt * 2 + j] = __ldg(att_src + col);
            da[nt * 2 + j] = __ldg(att_dst + col);
        }
    #pragma unroll
    for (int rt = 0; rt < 2; rt++)
        #pragma unroll
        for (int half = 0; half < 2; half++) {
            float ps = 0.f, pd = 0.f;
            #pragma unroll
            for (int nt = 0; nt < 8; nt++) {
                ps = fmaf(acc[rt][nt][half * 2 + 0], sa[nt * 2 + 0], ps);
                ps = fmaf(acc[rt][nt][half * 2 + 1], sa[nt * 2 + 1], ps);
                pd = fmaf(acc[rt][nt][half * 2 + 0], da[nt * 2 + 0], pd);
                pd = fmaf(acc[rt][nt][half * 2 + 1], da[nt * 2 + 1], pd);
            }
            ps += __shfl_xor_sync(0xffffffffu, ps, 1);
            ps += __shfl_xor_sync(0xffffffffu, ps, 2);
            pd += __shfl_xor_sync(0xffffffffu, pd, 1);
            pd += __shfl_xor_sync(0xffffffffu, pd, 2);
            if (q == 0) {
                int n = n0 + R + rt * 16 + half * 8 + p;
                if (n < N) {
                    g_as[((size_t)n * TT + t) * 2 + head] = ps;
                    g_ad[((size_t)n * TT + t) * 2 + head] = pd;
                }
            }
        }

    // ---- stage fp16 tile in smem, then coalesced dump ----
    __syncthreads();                 // done reading Xs
    __half* XsH = (__half*)smem;     // 64 x 128 fp16 = 16 KB
    #pragma unroll
    for (int rt = 0; rt < 2; rt++)
        #pragma unroll
        for (int nt = 0; nt < 8; nt++)
            #pragma unroll
            for (int half = 0; half < 2; half++) {
                int row = R + rt * 16 + half * 8 + p;
                int col = CB + nt * 8 + q * 2;
                __half2 hv = __floats2half2_rn(acc[rt][nt][half * 2 + 0],
                                               acc[rt][nt][half * 2 + 1]);
                *(__half2*)(XsH + row * HC + col) = hv;
            }
    __syncthreads();
    {
        __half* dstp = g_xl + ((size_t)t * N + n0) * HC;
        const uint4* s4 = (const uint4*)XsH;
        #pragma unroll
        for (int i = 0; i < 8; i++) {
            int idx = tid + i * 128;         // 1024 x 16B = 16 KB
            int n = n0 + (idx >> 4);
            if (n < N) ((uint4*)dstp)[idx] = s4[idx];
        }
    }
}

// ---------------- per (t, csr-pos) edge exp weights ----------------
__global__ __launch_bounds__(256) void k_edge(int E, int N) {
    int pos = blockIdx.x * blockDim.x + threadIdx.x;
    int t = blockIdx.y;
    if (pos >= E) return;
    int s = g_csr_src[pos];
    int d = g_csr_dst[pos];
    float2 a = *(const float2*)(g_as + ((size_t)s * TT + t) * 2);
    float2 b = *(const float2*)(g_ad + ((size_t)d * TT + t) * 2);
    float x0 = a.x + b.x, x1 = a.y + b.y;
    x0 = x0 > 0.f ? x0 : NEG_SLOPE * x0;
    x1 = x1 > 0.f ? x1 : NEG_SLOPE * x1;
    // scores bounded (|x| << 80): exp without max-subtraction is overflow-safe
    g_ex[(size_t)t * E + pos] = make_float2(__expf(x0), __expf(x1));
}

// ---------------- aggregation ----------------
// one warp per (t, dst-node); 32 lanes x 4 ch; lanes 0-15 head0, 16-31 head1.
__global__ __launch_bounds__(256) void k_agg(const float* __restrict__ bias,
                                             float* __restrict__ out, int N, int E) {
    int gw = (blockIdx.x * blockDim.x + threadIdx.x) >> 5;
    int lane = threadIdx.x & 31;
    if (gw >= TT * N) return;
    int t = gw / N, n = gw - t * N;

    const __half* xl = g_xl + (size_t)t * N * HC;
    const float2* exb = g_ex + (size_t)t * E;
    int s0 = g_off[n], s1 = g_off[n + 1];
    bool hh0 = lane < 16;

    float4 acc = make_float4(0.f, 0.f, 0.f, 0.f);
    float den = 0.f;
    for (int e = s0; e < s1; e++) {
        int srcn = __ldg(&g_csr_src[e]);          // uniform across warp
        float2 exv = __ldg(&exb[e]);
        float ex = hh0 ? exv.x : exv.y;
        den += ex;
        uint2 raw = *(const uint2*)(xl + (size_t)srcn * HC + lane * 4);
        float2 v01 = __half22float2(*(__half2*)&raw.x);
        float2 v23 = __half22float2(*(__half2*)&raw.y);
        acc.x = fmaf(ex, v01.x, acc.x);
        acc.y = fmaf(ex, v01.y, acc.y);
        acc.z = fmaf(ex, v23.x, acc.z);
        acc.w = fmaf(ex, v23.y, acc.w);
    }
    float inv = 1.f / den;
    acc.x *= inv; acc.y *= inv; acc.z *= inv; acc.w *= inv;

    float px = __shfl_down_sync(0xffffffffu, acc.x, 16);
    float py = __shfl_down_sync(0xffffffffu, acc.y, 16);
    float pz = __shfl_down_sync(0xffffffffu, acc.z, 16);
    float pw = __shfl_down_sync(0xffffffffu, acc.w, 16);
    if (hh0) {
        float4 b4 = *(const float4*)(bias + lane * 4);
        float4 o4;
        o4.x = 0.5f * (acc.x + px) + b4.x;
        o4.y = 0.5f * (acc.y + py) + b4.y;
        o4.z = 0.5f * (acc.z + pz) + b4.z;
        o4.w = 0.5f * (acc.w + pw) + b4.w;
        o4.x = o4.x > 0.f ? o4.x : (__expf(o4.x) - 1.f);
        o4.y = o4.y > 0.f ? o4.y : (__expf(o4.y) - 1.f);
        o4.z = o4.z > 0.f ? o4.z : (__expf(o4.z) - 1.f);
        o4.w = o4.w > 0.f ? o4.w : (__expf(o4.w) - 1.f);
        *(float4*)(out + ((size_t)n * TT + t) * 64 + lane * 4) = o4;
    }
}

extern "C" void kernel_launch(void* const* d_in, const int* in_sizes, int n_in,
                              void* d_out, int out_size) {
    const float* h       = (const float*)d_in[0];
    const int*   src     = (const int*)d_in[1];
    const int*   dst     = (const int*)d_in[2];
    const float* W       = (const float*)d_in[3];
    const float* att_src = (const float*)d_in[4];
    const float* att_dst = (const float*)d_in[5];
    const float* bias    = (const float*)d_in[6];
    float* out = (float*)d_out;

    int E = in_sizes[1];
    int N = in_sizes[0] / (TT * FIN);
    if (N > NMAX) N = NMAX;
    if (E > EMAX) E = EMAX;

    cudaFuncSetAttribute(k_gemm, cudaFuncAttributeMaxDynamicSharedMemorySize, GEMM_SMEM);

    // CSR build (timestep-invariant)
    k_zero_deg<<<(N + 255) / 256, 256>>>(N);
    k_count<<<(E + 255) / 256, 256>>>(dst, E);
    k_scan<<<1, 1024>>>(N);
    k_fill<<<(E + 255) / 256, 256>>>(src, dst, E);

    // tensor-core GEMM + fused scores (all timesteps)
    dim3 ggrid((N + 63) / 64, TT);
    k_gemm<<<ggrid, 128, GEMM_SMEM>>>(h, W, att_src, att_dst, N);

    // per-edge exp weights, CSR order (all timesteps)
    dim3 egrid((E + 255) / 256, TT);
    k_edge<<<egrid, 256>>>(E, N);

    // aggregation (softmax + message passing + head mean + bias + elu)
    int total_warps = TT * N;
    int ablocks = (total_warps * 32 + 255) / 256;
    k_agg<<<ablocks, 256>>>(bias, out, N, E);
}